// round 16
// baseline (speedup 1.0000x reference)
#include <cuda_runtime.h>

#define TM      16
#define NTH     256
#define DSTATE  256
#define DIN     512
#define NW      512
#define NSTEPS  60
#define NBLOCKS 128

typedef unsigned long long u64;

__constant__ float c_A[6][5] = {
    {0.f, 0.f, 0.f, 0.f, 0.f},
    {0.161f, 0.f, 0.f, 0.f, 0.f},
    {-0.008480655492356989f, 0.335480655492357f, 0.f, 0.f, 0.f},
    {2.8971530571054935f, -6.359448489975075f, 4.3622954328695815f, 0.f, 0.f},
    {5.325864828439257f, -11.748883564062828f, 7.4955393428898365f, -0.09249506636175525f, 0.f},
    {5.86145544294642f, -12.92096931784711f, 8.159367898576159f, -0.071584973281401f, -0.028269050394068383f}};
__constant__ float c_Bw[6] = {
    0.09646076681806523f, 0.01f, 0.4798896504144996f,
    1.379008574103742f, -3.290069515436081f, 2.324710524099774f};

// +4 rows pad: prefetch tails overread up to 4 k-rows (never consumed).
__device__ float g_W1T[(DIN + 4) * NW];
__device__ float g_W2T[(NW + 4) * NW];
__device__ float g_W3T[(NW + 4) * DSTATE];
__device__ float g_BU[NBLOCKS * NW * TM];   // per-CTA b1 + W1[:,256:]@u

static __device__ __forceinline__ u64 pk2(float x, float y) {
    u64 d; asm("mov.b64 %0, {%1, %2};" : "=l"(d) : "f"(x), "f"(y)); return d;
}
static __device__ __forceinline__ u64 fma2(u64 a, u64 b, u64 c) {
    u64 d; asm("fma.rn.f32x2 %0, %1, %2, %3;" : "=l"(d) : "l"(a), "l"(b), "l"(c)); return d;
}
static __device__ __forceinline__ void upk2(u64 v, float& x, float& y) {
    asm("mov.b64 {%0, %1}, %2;" : "=f"(x), "=f"(y) : "l"(v));
}

__global__ void transpose_kernel(int which, const float* __restrict__ src, int N, int K) {
    float* dst = (which == 0) ? g_W1T : (which == 1) ? g_W2T : g_W3T;
    __shared__ float tile[32][33];
    int kb = blockIdx.x * 32, nb = blockIdx.y * 32;
    int tx = threadIdx.x, ty = threadIdx.y;
    #pragma unroll
    for (int i = ty; i < 32; i += 8) tile[i][tx] = src[(nb + i) * K + (kb + tx)];
    __syncthreads();
    #pragma unroll
    for (int i = ty; i < 32; i += 8) dst[(kb + i) * N + (nb + tx)] = tile[tx][i];
}

// ======== full-K 8m x 4n GEMM: 256 threads cover all N=512 outputs ========
struct KG { float4 w; ulonglong2 a0, a1; };

static __device__ __forceinline__ KG ldg12(const float* __restrict__ Asm,
                                           const float* __restrict__ Wg, int ldw, int k) {
    KG g;
    g.w = *reinterpret_cast<const float4*>(Wg + (size_t)k * ldw);
    const float* ar = Asm + k * TM;
    g.a0 = *reinterpret_cast<const ulonglong2*>(ar);
    g.a1 = *reinterpret_cast<const ulonglong2*>(ar + 4);
    return g;
}

static __device__ __forceinline__ void cmp12(const KG& g, u64* __restrict__ acc) {
    float wv[4] = {g.w.x, g.w.y, g.w.z, g.w.w};
    u64 p0 = g.a0.x, p1 = g.a0.y, p2 = g.a1.x, p3 = g.a1.y;
    #pragma unroll
    for (int nj = 0; nj < 4; ++nj) {
        u64 wd = pk2(wv[nj], wv[nj]);
        acc[nj * 4 + 0] = fma2(p0, wd, acc[nj * 4 + 0]);
        acc[nj * 4 + 1] = fma2(p1, wd, acc[nj * 4 + 1]);
        acc[nj * 4 + 2] = fma2(p2, wd, acc[nj * 4 + 2]);
        acc[nj * 4 + 3] = fma2(p3, wd, acc[nj * 4 + 3]);
    }
}

// K multiple of 8; tail overreads <=3 rows past K (A: adjacent SMEM, W: padded).
// Loads are offset by m0/n0 HERE (R15 bug: epilogue-only offsets).
template <bool ADDVEC, bool ADDBIAS, bool RELU>
static __device__ __forceinline__ void gemm12(
    const float* __restrict__ Asm_base, const float* __restrict__ Wg_base, int ldw, int K,
    const float* __restrict__ addvec, const float* __restrict__ bias,
    float* __restrict__ dst, int n0, int m0) {
    const float* Asm = Asm_base + m0;     // <<< fix
    const float* Wg = Wg_base + n0;       // <<< fix
    u64 acc[16];
    #pragma unroll
    for (int i = 0; i < 16; ++i) acc[i] = 0ull;
    KG b0 = ldg12(Asm, Wg, ldw, 0);
    KG b1 = ldg12(Asm, Wg, ldw, 1);
    KG b2 = ldg12(Asm, Wg, ldw, 2);
    KG b3 = ldg12(Asm, Wg, ldw, 3);
    #pragma unroll 1
    for (int k = 0; k < K; k += 8) {
        KG c0 = ldg12(Asm, Wg, ldw, k + 4);
        KG c1 = ldg12(Asm, Wg, ldw, k + 5);
        KG c2 = ldg12(Asm, Wg, ldw, k + 6);
        KG c3 = ldg12(Asm, Wg, ldw, k + 7);
        cmp12(b0, acc); cmp12(b1, acc); cmp12(b2, acc); cmp12(b3, acc);
        b0 = ldg12(Asm, Wg, ldw, k + 8);
        b1 = ldg12(Asm, Wg, ldw, k + 9);
        b2 = ldg12(Asm, Wg, ldw, k + 10);
        b3 = ldg12(Asm, Wg, ldw, k + 11);
        cmp12(c0, acc); cmp12(c1, acc); cmp12(c2, acc); cmp12(c3, acc);
    }
    #pragma unroll
    for (int nj = 0; nj < 4; ++nj) {
        float x[8];
        upk2(acc[nj * 4 + 0], x[0], x[1]);
        upk2(acc[nj * 4 + 1], x[2], x[3]);
        upk2(acc[nj * 4 + 2], x[4], x[5]);
        upk2(acc[nj * 4 + 3], x[6], x[7]);
        if (ADDVEC) {
            const float* av = addvec + (n0 + nj) * TM + m0;
            float4 v0 = *reinterpret_cast<const float4*>(av);
            float4 v1 = *reinterpret_cast<const float4*>(av + 4);
            x[0] += v0.x; x[1] += v0.y; x[2] += v0.z; x[3] += v0.w;
            x[4] += v1.x; x[5] += v1.y; x[6] += v1.z; x[7] += v1.w;
        }
        if (ADDBIAS) {
            float bb = bias[n0 + nj];
            #pragma unroll
            for (int t = 0; t < 8; ++t) x[t] += bb;
        }
        if (RELU) {
            #pragma unroll
            for (int t = 0; t < 8; ++t) x[t] = fmaxf(x[t], 0.f);
        }
        float* dp = dst + (n0 + nj) * TM + m0;
        *reinterpret_cast<float4*>(dp) = make_float4(x[0], x[1], x[2], x[3]);
        *reinterpret_cast<float4*>(dp + 4) = make_float4(x[4], x[5], x[6], x[7]);
    }
}

// ======== gemm3: R5-proven 8m x 8n, 4-way k-split ========
struct KB8 { float4 w0, w1; ulonglong2 a0, a1; };

static __device__ __forceinline__ KB8 ldk(const float* __restrict__ Asm,
                                          const float* __restrict__ Wg, int ldw, int k) {
    KB8 b;
    const float* wr = Wg + (size_t)k * ldw;
    b.w0 = *reinterpret_cast<const float4*>(wr);
    b.w1 = *reinterpret_cast<const float4*>(wr + 4);
    const float* ar = Asm + k * TM;
    b.a0 = *reinterpret_cast<const ulonglong2*>(ar);
    b.a1 = *reinterpret_cast<const ulonglong2*>(ar + 4);
    return b;
}

static __device__ __forceinline__ void cmp8(const KB8& b, u64* __restrict__ acc) {
    float wv[8] = {b.w0.x, b.w0.y, b.w0.z, b.w0.w, b.w1.x, b.w1.y, b.w1.z, b.w1.w};
    u64 p0 = b.a0.x, p1 = b.a0.y, p2 = b.a1.x, p3 = b.a1.y;
    #pragma unroll
    for (int nj = 0; nj < 8; ++nj) {
        u64 wd = pk2(wv[nj], wv[nj]);
        acc[nj * 4 + 0] = fma2(p0, wd, acc[nj * 4 + 0]);
        acc[nj * 4 + 1] = fma2(p1, wd, acc[nj * 4 + 1]);
        acc[nj * 4 + 2] = fma2(p2, wd, acc[nj * 4 + 2]);
        acc[nj * 4 + 3] = fma2(p3, wd, acc[nj * 4 + 3]);
    }
}

static __device__ __forceinline__ void mma8x8(
    const float* __restrict__ Asm, const float* __restrict__ Wg,
    int ldw, int KH, u64* __restrict__ acc) {
    KB8 b0 = ldk(Asm, Wg, ldw, 0);
    KB8 b1 = ldk(Asm, Wg, ldw, 1);
    #pragma unroll 1
    for (int k = 0; k < KH; k += 4) {
        KB8 c0 = ldk(Asm, Wg, ldw, k + 2);
        KB8 c1 = ldk(Asm, Wg, ldw, k + 3);
        cmp8(b0, acc);
        cmp8(b1, acc);
        b0 = ldk(Asm, Wg, ldw, k + 4);
        b1 = ldk(Asm, Wg, ldw, k + 5);
        cmp8(c0, acc);
        cmp8(c1, acc);
    }
}

static __device__ __forceinline__ void store_partial(
    float* __restrict__ dst, int n0, int m0, const u64* __restrict__ acc) {
    #pragma unroll
    for (int nj = 0; nj < 8; ++nj) {
        ulonglong2 v, w;
        v.x = acc[nj * 4 + 0]; v.y = acc[nj * 4 + 1];
        w.x = acc[nj * 4 + 2]; w.y = acc[nj * 4 + 3];
        *reinterpret_cast<ulonglong2*>(dst + (n0 + nj) * TM + m0) = v;
        *reinterpret_cast<ulonglong2*>(dst + (n0 + nj) * TM + m0 + 4) = w;
    }
}

// ======== main fused Tsit5 kernel ========
__global__ void __launch_bounds__(NTH, 1)
ode_main(const float* __restrict__ x0, const float* __restrict__ uf,
         const float* __restrict__ b1, const float* __restrict__ b2,
         const float* __restrict__ b3, float* __restrict__ out) {
    extern __shared__ float smem[];
    float* A0 = smem;                 // [512][16] z (rows 0-255) / h2
    float* A1 = A0 + NW * TM;         // [512][16] h1 / gemm3 partial q3
    float* P  = A1 + NW * TM;         // [512][16] gemm3 partials q1,q2
    float* Y  = P + NW * TM;          // [256][16]
    float* KB = Y + DSTATE * TM;      // [6][256][16]

    const int tid = threadIdx.x;
    const int r0 = blockIdx.x * TM;
    float* BUg = g_BU + (size_t)blockIdx.x * (NW * TM);

    // full-K gemm12 mapping: 2m x 128n
    const int m0g = (tid & 1) * 8;
    const int n0g = (tid >> 1) * 4;
    // gemm3: 4-way k-split, 2m x 32n
    const int q = tid >> 6;
    const int pos3 = tid & 63;
    const int m3 = (pos3 & 1) * 8;
    const int n3 = (pos3 >> 1) * 8;

    // init Y; u into A0 rows 0-255 for BU precompute
    for (int idx = tid; idx < TM * DSTATE; idx += NTH) {
        int m = idx >> 8, c = idx & 255;
        int r = r0 + m, traj = r & 1023;
        Y[c * TM + m] = x0[traj * DSTATE + c];
        A0[c * TM + m] = (r < 1024) ? uf[traj * DSTATE + c] : 0.f;
    }
    __syncthreads();

    // BU = b1 + W1[:,256:512] @ u  (once)
    gemm12<false, true, false>(A0, g_W1T + (size_t)DSTATE * NW, NW, 256,
                               nullptr, b1, BUg, n0g, m0g);
    __syncthreads();
    // first stage input: z = y0
    for (int i4 = tid; i4 < (DSTATE * TM) / 4; i4 += NTH)
        reinterpret_cast<float4*>(A0)[i4] = reinterpret_cast<const float4*>(Y)[i4];
    __syncthreads();

    const float H = 1.0f / 60.0f;

    #pragma unroll 1
    for (int step = 0; step < NSTEPS; ++step) {
        #pragma unroll 1
        for (int s = 0; s < 6; ++s) {
            // gemm1: A1 = relu(BU + W1[:, :256] @ z), full K=256, direct write
            gemm12<true, false, true>(A0, g_W1T, NW, 256, BUg, nullptr, A1, n0g, m0g);
            __syncthreads();
            // gemm2: A0 = relu(b2 + W2 @ h1), full K=512, direct write
            gemm12<false, true, true>(A1, g_W2T, NW, 512, nullptr, b2, A0, n0g, m0g);
            __syncthreads();
            // gemm3 partials: k_s = b3 + W3 @ h2, 4-way k-split
            float* KBs = KB + s * DSTATE * TM;
            {
                u64 acc[32];
                #pragma unroll
                for (int i = 0; i < 32; ++i) acc[i] = 0ull;
                mma8x8(A0 + q * 128 * TM + m3,
                       g_W3T + (size_t)(q * 128) * DSTATE + n3, DSTATE, 128, acc);
                float* pdst = (q == 0) ? KBs : (q == 1) ? P
                              : (q == 2) ? (P + DSTATE * TM) : A1;
                store_partial(pdst, n3, m3, acc);
            }
            __syncthreads();
            // combine + fused next-z build (or y-update on s==5) -> A0 rows [0,256)
            {
                float cf[6];
                if (s < 5) {
                    #pragma unroll
                    for (int j = 0; j < 5; ++j) cf[j] = (j <= s) ? c_A[s + 1][j] : 0.f;
                    cf[5] = 0.f;
                } else {
                    #pragma unroll
                    for (int j = 0; j < 6; ++j) cf[j] = c_Bw[j];
                }
                for (int i4 = tid; i4 < (DSTATE * TM) / 4; i4 += NTH) {
                    float4 v  = reinterpret_cast<const float4*>(KBs)[i4];
                    float4 p1 = reinterpret_cast<const float4*>(P)[i4];
                    float4 p2 = reinterpret_cast<const float4*>(P + DSTATE * TM)[i4];
                    float4 p3 = reinterpret_cast<const float4*>(A1)[i4];
                    float bb = b3[i4 >> 2];
                    v.x += p1.x + p2.x + p3.x + bb;
                    v.y += p1.y + p2.y + p3.y + bb;
                    v.z += p1.z + p2.z + p3.z + bb;
                    v.w += p1.w + p2.w + p3.w + bb;
                    if (s < 5) reinterpret_cast<float4*>(KBs)[i4] = v;
                    float cs = cf[s];
                    float4 a = make_float4(cs * v.x, cs * v.y, cs * v.z, cs * v.w);
                    for (int j = 0; j < s; ++j) {
                        float4 kv = reinterpret_cast<const float4*>(KB + j * DSTATE * TM)[i4];
                        float cj = cf[j];
                        a.x += cj * kv.x; a.y += cj * kv.y;
                        a.z += cj * kv.z; a.w += cj * kv.w;
                    }
                    float4 y = reinterpret_cast<const float4*>(Y)[i4];
                    y.x += H * a.x; y.y += H * a.y; y.z += H * a.z; y.w += H * a.w;
                    if (s == 5) reinterpret_cast<float4*>(Y)[i4] = y;
                    reinterpret_cast<float4*>(A0)[i4] = y;   // z for next stage / y_new
                }
            }
            __syncthreads();
        }
    }

    for (int idx = tid; idx < TM * DSTATE; idx += NTH) {
        int m = idx >> 8, c = idx & 255;
        out[(size_t)(r0 + m) * DSTATE + c] = Y[c * TM + m];
    }
}

// ---------------- launch ----------------
extern "C" void kernel_launch(void* const* d_in, const int* in_sizes, int n_in,
                              void* d_out, int out_size) {
    (void)in_sizes; (void)n_in; (void)out_size;
    const float* x0 = (const float*)d_in[0];
    const float* uf = (const float*)d_in[1];
    const float* W1 = (const float*)d_in[2];
    const float* b1 = (const float*)d_in[3];
    const float* W2 = (const float*)d_in[4];
    const float* b2 = (const float*)d_in[5];
    const float* W3 = (const float*)d_in[6];
    const float* b3 = (const float*)d_in[7];
    float* out = (float*)d_out;

    dim3 tthreads(32, 8);
    transpose_kernel<<<dim3(DIN / 32, NW / 32), tthreads>>>(0, W1, NW, DIN);
    transpose_kernel<<<dim3(NW / 32, NW / 32), tthreads>>>(1, W2, NW, NW);
    transpose_kernel<<<dim3(NW / 32, DSTATE / 32), tthreads>>>(2, W3, DSTATE, NW);

    size_t smem_bytes = (size_t)(3 * NW * TM + 7 * DSTATE * TM) * sizeof(float);
    cudaFuncSetAttribute(ode_main, cudaFuncAttributeMaxDynamicSharedMemorySize, (int)smem_bytes);
    ode_main<<<NBLOCKS, NTH, smem_bytes>>>(x0, uf, b1, b2, b3, out);
}

// round 17
// speedup vs baseline: 1.0643x; 1.0643x over previous
#include <cuda_runtime.h>

#define TM      16
#define NTH     256
#define DSTATE  256
#define DIN     512
#define NW      512
#define NSTEPS  60
#define NBLOCKS 128

typedef unsigned long long u64;

__constant__ float c_A[6][5] = {
    {0.f, 0.f, 0.f, 0.f, 0.f},
    {0.161f, 0.f, 0.f, 0.f, 0.f},
    {-0.008480655492356989f, 0.335480655492357f, 0.f, 0.f, 0.f},
    {2.8971530571054935f, -6.359448489975075f, 4.3622954328695815f, 0.f, 0.f},
    {5.325864828439257f, -11.748883564062828f, 7.4955393428898365f, -0.09249506636175525f, 0.f},
    {5.86145544294642f, -12.92096931784711f, 8.159367898576159f, -0.071584973281401f, -0.028269050394068383f}};
__constant__ float c_Bw[6] = {
    0.09646076681806523f, 0.01f, 0.4798896504144996f,
    1.379008574103742f, -3.290069515436081f, 2.324710524099774f};

// +4 rows of padding: prefetch tails overread up to 2 k-rows (never consumed).
__device__ float g_W1T[(DIN + 4) * NW];
__device__ float g_W2T[(NW + 4) * NW];
__device__ float g_W3T[(NW + 4) * DSTATE];
__device__ float g_BU[NBLOCKS * NW * TM];   // per-CTA b1 + W1[:,256:]@u

// ---------------- packed f32x2 helpers ----------------
static __device__ __forceinline__ u64 pk2(float x, float y) {
    u64 d; asm("mov.b64 %0, {%1, %2};" : "=l"(d) : "f"(x), "f"(y)); return d;
}
static __device__ __forceinline__ u64 fma2(u64 a, u64 b, u64 c) {
    u64 d; asm("fma.rn.f32x2 %0, %1, %2, %3;" : "=l"(d) : "l"(a), "l"(b), "l"(c)); return d;
}

// ---------------- weight transpose: src[N][K] -> dst[K][N] ----------------
__global__ void transpose_kernel(int which, const float* __restrict__ src, int N, int K) {
    float* dst = (which == 0) ? g_W1T : (which == 1) ? g_W2T : g_W3T;
    __shared__ float tile[32][33];
    int kb = blockIdx.x * 32, nb = blockIdx.y * 32;
    int tx = threadIdx.x, ty = threadIdx.y;
    #pragma unroll
    for (int i = ty; i < 32; i += 8) tile[i][tx] = src[(nb + i) * K + (kb + tx)];
    __syncthreads();
    #pragma unroll
    for (int i = ty; i < 32; i += 8) dst[(kb + i) * N + (nb + tx)] = tile[tx][i];
}

// ---------------- 8m x 8n register-tile GEMM (R5-exact) ----------------
struct KB8 { float4 w0, w1; ulonglong2 a0, a1; };

static __device__ __forceinline__ KB8 ldk(const float* __restrict__ Asm,
                                          const float* __restrict__ Wg,
                                          int ldw, int k) {
    KB8 b;
    const float* wr = Wg + (size_t)k * ldw;
    b.w0 = *reinterpret_cast<const float4*>(wr);
    b.w1 = *reinterpret_cast<const float4*>(wr + 4);
    const float* ar = Asm + k * TM;
    b.a0 = *reinterpret_cast<const ulonglong2*>(ar);
    b.a1 = *reinterpret_cast<const ulonglong2*>(ar + 4);
    return b;
}

static __device__ __forceinline__ void cmp8(const KB8& b, u64* __restrict__ acc) {
    float wv[8] = {b.w0.x, b.w0.y, b.w0.z, b.w0.w, b.w1.x, b.w1.y, b.w1.z, b.w1.w};
    u64 ap0 = b.a0.x, ap1 = b.a0.y, ap2 = b.a1.x, ap3 = b.a1.y;
    #pragma unroll
    for (int nj = 0; nj < 8; ++nj) {
        u64 wd = pk2(wv[nj], wv[nj]);
        acc[nj * 4 + 0] = fma2(ap0, wd, acc[nj * 4 + 0]);
        acc[nj * 4 + 1] = fma2(ap1, wd, acc[nj * 4 + 1]);
        acc[nj * 4 + 2] = fma2(ap2, wd, acc[nj * 4 + 2]);
        acc[nj * 4 + 3] = fma2(ap3, wd, acc[nj * 4 + 3]);
    }
}

// KH multiple of 4. Tail prefetch overreads up to 2 rows past KH in both
// Asm (adjacent live SMEM buffer) and Wg (padded arrays).
static __device__ __forceinline__ void mma8x8(
    const float* __restrict__ Asm, const float* __restrict__ Wg,
    int ldw, int KH, u64* __restrict__ acc) {
    KB8 b0 = ldk(Asm, Wg, ldw, 0);
    KB8 b1 = ldk(Asm, Wg, ldw, 1);
    #pragma unroll 1
    for (int k = 0; k < KH; k += 4) {
        KB8 c0 = ldk(Asm, Wg, ldw, k + 2);
        KB8 c1 = ldk(Asm, Wg, ldw, k + 3);
        cmp8(b0, acc);
        cmp8(b1, acc);
        b0 = ldk(Asm, Wg, ldw, k + 4);
        b1 = ldk(Asm, Wg, ldw, k + 5);
        cmp8(c0, acc);
        cmp8(c1, acc);
    }
}

static __device__ __forceinline__ void store_partial(
    float* __restrict__ dst, int n0, int m0, const u64* __restrict__ acc) {
    #pragma unroll
    for (int nj = 0; nj < 8; ++nj) {
        ulonglong2 v, w;
        v.x = acc[nj * 4 + 0]; v.y = acc[nj * 4 + 1];
        w.x = acc[nj * 4 + 2]; w.y = acc[nj * 4 + 3];
        *reinterpret_cast<ulonglong2*>(dst + (n0 + nj) * TM + m0) = v;
        *reinterpret_cast<ulonglong2*>(dst + (n0 + nj) * TM + m0 + 4) = w;
    }
}

static __device__ __forceinline__ void zero_acc(u64* acc) {
    #pragma unroll
    for (int i = 0; i < 32; ++i) acc[i] = 0ull;
}

// ---------------- main fused Tsit5 kernel ----------------
__global__ void __launch_bounds__(NTH, 1)
ode_main(const float* __restrict__ x0, const float* __restrict__ uf,
         const float* __restrict__ b1, const float* __restrict__ b2,
         const float* __restrict__ b3, float* __restrict__ out) {
    extern __shared__ float smem[];
    float* A0 = smem;                 // [512][16] z (rows 0-255) / h2
    float* A1 = A0 + NW * TM;         // [512][16] h1 / gemm3 partial q3
    float* P  = A1 + NW * TM;         // [512][16] partials
    float* Y  = P + NW * TM;          // [256][16]
    float* KB = Y + DSTATE * TM;      // [6][256][16]

    const int tid = threadIdx.x;
    const int r0 = blockIdx.x * TM;
    float* BUg = g_BU + (size_t)blockIdx.x * (NW * TM);

    // N=512 gemms: 2-way k-split, 128 positions (2m x 64n)
    const int half = tid >> 7;
    const int pos = tid & 127;
    const int m0 = (pos & 1) * 8;
    const int n0 = (pos >> 1) * 8;
    // gemm3 (N=256): 4-way k-split, 64 positions
    const int q = tid >> 6;
    const int pos3 = tid & 63;
    const int m3 = (pos3 & 1) * 8;
    const int n3 = (pos3 >> 1) * 8;

    // init Y; u into A0 rows 0-255 (k-major) for BU precompute
    for (int idx = tid; idx < TM * DSTATE; idx += NTH) {
        int m = idx >> 8, c = idx & 255;
        int r = r0 + m, traj = r & 1023;
        Y[c * TM + m] = x0[traj * DSTATE + c];
        A0[c * TM + m] = (r < 1024) ? uf[traj * DSTATE + c] : 0.f;
    }
    __syncthreads();

    // ---- BU = b1 + W1[:,256:512] @ u ----
    {
        u64 acc[32];
        zero_acc(acc);
        mma8x8(A0 + half * 128 * TM + m0,
               g_W1T + (size_t)(DSTATE + half * 128) * NW + n0, NW, 128, acc);
        store_partial(half ? P : A1, n0, m0, acc);
        __syncthreads();
        for (int i4 = tid; i4 < (NW * TM) / 4; i4 += NTH) {
            float4 a = reinterpret_cast<const float4*>(A1)[i4];
            float4 p = reinterpret_cast<const float4*>(P)[i4];
            float bb = b1[i4 >> 2];
            reinterpret_cast<float4*>(BUg)[i4] =
                make_float4(a.x + p.x + bb, a.y + p.y + bb, a.z + p.z + bb, a.w + p.w + bb);
        }
        __syncthreads();
    }

    // first stage input: z = y0 into A0 rows [0,256)
    for (int i4 = tid; i4 < (DSTATE * TM) / 4; i4 += NTH)
        reinterpret_cast<float4*>(A0)[i4] = reinterpret_cast<const float4*>(Y)[i4];
    __syncthreads();

    const float H = 1.0f / 60.0f;

    #pragma unroll 1
    for (int step = 0; step < NSTEPS; ++step) {
        #pragma unroll 1
        for (int s = 0; s < 6; ++s) {
            // gemm1: A1 = relu(BU + W1[:, :256] @ z), K=256, 2-way k-split
            {
                u64 acc[32];
                zero_acc(acc);
                mma8x8(A0 + half * 128 * TM + m0,
                       g_W1T + (size_t)(half * 128) * NW + n0, NW, 128, acc);
                store_partial(half ? P : A1, n0, m0, acc);
                __syncthreads();
                for (int i4 = tid; i4 < (NW * TM) / 4; i4 += NTH) {
                    float4 a = reinterpret_cast<const float4*>(A1)[i4];
                    float4 p = reinterpret_cast<const float4*>(P)[i4];
                    float4 bu = reinterpret_cast<const float4*>(BUg)[i4];
                    float4 v;
                    v.x = fmaxf(a.x + p.x + bu.x, 0.f);
                    v.y = fmaxf(a.y + p.y + bu.y, 0.f);
                    v.z = fmaxf(a.z + p.z + bu.z, 0.f);
                    v.w = fmaxf(a.w + p.w + bu.w, 0.f);
                    reinterpret_cast<float4*>(A1)[i4] = v;
                }
                __syncthreads();
            }
            // gemm2: A0 = relu(b2 + W2 @ h1), K=512, 2-way k-split
            {
                u64 acc[32];
                zero_acc(acc);
                mma8x8(A1 + half * 256 * TM + m0,
                       g_W2T + (size_t)(half * 256) * NW + n0, NW, 256, acc);
                store_partial(half ? P : A0, n0, m0, acc);
                __syncthreads();
                for (int i4 = tid; i4 < (NW * TM) / 4; i4 += NTH) {
                    float4 a = reinterpret_cast<const float4*>(A0)[i4];
                    float4 p = reinterpret_cast<const float4*>(P)[i4];
                    float bb = b2[i4 >> 2];
                    float4 v;
                    v.x = fmaxf(a.x + p.x + bb, 0.f);
                    v.y = fmaxf(a.y + p.y + bb, 0.f);
                    v.z = fmaxf(a.z + p.z + bb, 0.f);
                    v.w = fmaxf(a.w + p.w + bb, 0.f);
                    reinterpret_cast<float4*>(A0)[i4] = v;
                }
                __syncthreads();
            }
            // gemm3: k_s partials = W3 @ h2, K=512, N=256, 4-way k-split
            float* KBs = KB + s * DSTATE * TM;
            {
                u64 acc[32];
                zero_acc(acc);
                mma8x8(A0 + q * 128 * TM + m3,
                       g_W3T + (size_t)(q * 128) * DSTATE + n3, DSTATE, 128, acc);
                float* pdst = (q == 0) ? KBs : (q == 1) ? P : (q == 2) ? (P + DSTATE * TM) : A1;
                store_partial(pdst, n3, m3, acc);
                __syncthreads();
            }
            // fused: combine k_s + build next z (or y-update at s==5) -> A0 rows [0,256)
            {
                float cf[6];
                if (s < 5) {
                    #pragma unroll
                    for (int j = 0; j < 5; ++j) cf[j] = (j <= s) ? c_A[s + 1][j] : 0.f;
                    cf[5] = 0.f;
                } else {
                    #pragma unroll
                    for (int j = 0; j < 6; ++j) cf[j] = c_Bw[j];
                }
                for (int i4 = tid; i4 < (DSTATE * TM) / 4; i4 += NTH) {
                    float4 v  = reinterpret_cast<const float4*>(KBs)[i4];
                    float4 p1 = reinterpret_cast<const float4*>(P)[i4];
                    float4 p2 = reinterpret_cast<const float4*>(P + DSTATE * TM)[i4];
                    float4 p3 = reinterpret_cast<const float4*>(A1)[i4];
                    float bb = b3[i4 >> 2];
                    v.x += p1.x + p2.x + p3.x + bb;
                    v.y += p1.y + p2.y + p3.y + bb;
                    v.z += p1.z + p2.z + p3.z + bb;
                    v.w += p1.w + p2.w + p3.w + bb;
                    if (s < 5) reinterpret_cast<float4*>(KBs)[i4] = v;
                    float cs = cf[s];
                    float4 a = make_float4(cs * v.x, cs * v.y, cs * v.z, cs * v.w);
                    for (int j = 0; j < s; ++j) {
                        float4 kv = reinterpret_cast<const float4*>(KB + j * DSTATE * TM)[i4];
                        float cj = cf[j];
                        a.x += cj * kv.x; a.y += cj * kv.y;
                        a.z += cj * kv.z; a.w += cj * kv.w;
                    }
                    float4 y = reinterpret_cast<const float4*>(Y)[i4];
                    y.x += H * a.x; y.y += H * a.y; y.z += H * a.z; y.w += H * a.w;
                    if (s == 5) reinterpret_cast<float4*>(Y)[i4] = y;
                    reinterpret_cast<float4*>(A0)[i4] = y;   // z for next stage / y_new
                }
            }
            __syncthreads();
        }
    }

    for (int idx = tid; idx < TM * DSTATE; idx += NTH) {
        int m = idx >> 8, c = idx & 255;
        out[(size_t)(r0 + m) * DSTATE + c] = Y[c * TM + m];
    }
}

// ---------------- launch ----------------
extern "C" void kernel_launch(void* const* d_in, const int* in_sizes, int n_in,
                              void* d_out, int out_size) {
    (void)in_sizes; (void)n_in; (void)out_size;
    const float* x0 = (const float*)d_in[0];
    const float* uf = (const float*)d_in[1];
    const float* W1 = (const float*)d_in[2];
    const float* b1 = (const float*)d_in[3];
    const float* W2 = (const float*)d_in[4];
    const float* b2 = (const float*)d_in[5];
    const float* W3 = (const float*)d_in[6];
    const float* b3 = (const float*)d_in[7];
    float* out = (float*)d_out;

    dim3 tthreads(32, 8);
    transpose_kernel<<<dim3(DIN / 32, NW / 32), tthreads>>>(0, W1, NW, DIN);
    transpose_kernel<<<dim3(NW / 32, NW / 32), tthreads>>>(1, W2, NW, NW);
    transpose_kernel<<<dim3(NW / 32, DSTATE / 32), tthreads>>>(2, W3, DSTATE, NW);

    size_t smem_bytes = (size_t)(3 * NW * TM + 7 * DSTATE * TM) * sizeof(float);
    cudaFuncSetAttribute(ode_main, cudaFuncAttributeMaxDynamicSharedMemorySize, (int)smem_bytes);
    ode_main<<<NBLOCKS, NTH, smem_bytes>>>(x0, uf, b1, b2, b3, out);
}